// round 2
// baseline (speedup 1.0000x reference)
#include <cuda_runtime.h>
#include <cstdint>

#define NN   50000
#define EE   500000
#define DD   256
#define KTOT 768   // 3 * DD

// ---------------- scratch (static device globals; no allocation) ----------------
__device__ float g_agg[(size_t)NN * KTOT];   // [node][r*256+d] summed source features
__device__ float g_cnt[3 * NN];              // [r][node] edge counts (as float)
__device__ int   g_is64;                     // index dtype flag

// ---------------- index dtype detection (int32 vs int64) ----------------
// For int64 little-endian values < 50000, every odd 32-bit word is 0.
// For int32 random values in [0,50000), 32 consecutive odd words all being
// zero has probability ~(2e-5)^32 — effectively impossible.
__global__ void detect_kernel(const int* __restrict__ src) {
    if (threadIdx.x == 0 && blockIdx.x == 0) {
        int ok = 1;
#pragma unroll
        for (int i = 0; i < 32; i++)
            if (src[2 * i + 1] != 0) ok = 0;
        g_is64 = ok;
    }
}

// ---------------- zero scratch ----------------
__global__ void zero_kernel() {
    size_t i = (size_t)blockIdx.x * blockDim.x + threadIdx.x;
    const size_t n4 = (size_t)NN * KTOT / 4;      // 9.6M float4
    float4 z = make_float4(0.f, 0.f, 0.f, 0.f);
    if (i < n4)            reinterpret_cast<float4*>(g_agg)[i] = z;
    if (i < (size_t)(3 * NN) / 4) reinterpret_cast<float4*>(g_cnt)[i] = z;
    // 3*NN = 150000 is divisible by 4 (150000/4 = 37500), so no tail.
}

// ---------------- edge aggregation: one warp per edge, all 3 relations ----------------
// gathers features[src] (L2-resident, 51.2 MB) and vector-REDs into g_agg[dst]
__global__ __launch_bounds__(256) void edge_kernel(
    const void* __restrict__ src0, const void* __restrict__ dst0,
    const void* __restrict__ src1, const void* __restrict__ dst1,
    const void* __restrict__ src2, const void* __restrict__ dst2,
    const float* __restrict__ feat)
{
    int e = (int)(((size_t)blockIdx.x * blockDim.x + threadIdx.x) >> 5);
    if (e >= EE) return;
    const int seg  = blockIdx.z;
    const int lane = threadIdx.x & 31;

    const void* src = (seg == 0) ? src0 : ((seg == 1) ? src1 : src2);
    const void* dst = (seg == 0) ? dst0 : ((seg == 1) ? dst1 : dst2);

    int s, d;
    if (g_is64) {
        s = (int)((const long long*)src)[e];
        d = (int)((const long long*)dst)[e];
    } else {
        s = ((const int*)src)[e];
        d = ((const int*)dst)[e];
    }
    if ((unsigned)s >= NN || (unsigned)d >= NN) return;  // safety net

    const float4* f = reinterpret_cast<const float4*>(feat + (size_t)s * DD);
    float* a = g_agg + (size_t)d * KTOT + (size_t)seg * DD;

    float4 v0 = f[lane];
    float4 v1 = f[lane + 32];
    asm volatile("red.global.add.v4.f32 [%0], {%1,%2,%3,%4};"
                 :: "l"(a + 4 * lane), "f"(v0.x), "f"(v0.y), "f"(v0.z), "f"(v0.w) : "memory");
    asm volatile("red.global.add.v4.f32 [%0], {%1,%2,%3,%4};"
                 :: "l"(a + 4 * (lane + 32)), "f"(v1.x), "f"(v1.y), "f"(v1.z), "f"(v1.w) : "memory");
    if (lane == 0)
        atomicAdd(&g_cnt[seg * NN + d], 1.0f);
}

// ---------------- fused GEMM + mean + bias + relu ----------------
// out[m,n] = relu( sum_seg (agg[m, seg*256: ] * inv_cnt[seg][m]) @ W_seg[:,n]
//                  + sum_seg flag[seg][m] * b_seg[n] )
#define BM 128
#define BN 128
#define BK 16

__global__ __launch_bounds__(256) void gemm_kernel(
    const float* __restrict__ W0, const float* __restrict__ b0,
    const float* __restrict__ W1, const float* __restrict__ b1,
    const float* __restrict__ W2, const float* __restrict__ b2,
    float* __restrict__ out)
{
    __shared__ float As[BK][BM + 4];   // padded pitch 132 -> conflict-free transposed stores
    __shared__ float Bs[BK][BN];
    __shared__ float s_inv[3][BM];
    __shared__ float s_flg[3][BM];

    const int m0 = blockIdx.x * BM;
    const int n0 = blockIdx.y * BN;
    const int t  = threadIdx.x;
    const int tx = t & 15;     // 16 cols of threads
    const int ty = t >> 4;     // 16 rows of threads

    // per-row 1/cnt and presence flags
    if (t < BM) {
        int row = m0 + t;
#pragma unroll
        for (int r = 0; r < 3; r++) {
            float c = (row < NN) ? g_cnt[r * NN + row] : 0.f;
            s_inv[r][t] = (c > 0.f) ? (1.f / c) : 0.f;
            s_flg[r][t] = (c > 0.f) ? 1.f : 0.f;
        }
    }

    float acc[8][8];
#pragma unroll
    for (int i = 0; i < 8; i++)
#pragma unroll
        for (int j = 0; j < 8; j++) acc[i][j] = 0.f;

#pragma unroll 1
    for (int seg = 0; seg < 3; seg++) {
        const float* Wp = (seg == 0) ? W0 : ((seg == 1) ? W1 : W2);
#pragma unroll 1
        for (int kt = 0; kt < DD; kt += BK) {
            const int k0 = seg * DD + kt;

            __syncthreads();   // prev compute done (and s_inv ready on first iter)

            // ---- load A tile (128 x 16), scaled by inv_cnt; store transposed ----
#pragma unroll
            for (int pass = 0; pass < 2; pass++) {
                int rowA = (t >> 2) + pass * 64;
                int kq   = (t & 3) * 4;
                int grow = m0 + rowA;
                float4 v = make_float4(0.f, 0.f, 0.f, 0.f);
                if (grow < NN)
                    v = *reinterpret_cast<const float4*>(&g_agg[(size_t)grow * KTOT + k0 + kq]);
                float inv = s_inv[seg][rowA];
                As[kq + 0][rowA] = v.x * inv;
                As[kq + 1][rowA] = v.y * inv;
                As[kq + 2][rowA] = v.z * inv;
                As[kq + 3][rowA] = v.w * inv;
            }

            // ---- load B tile (16 x 128) from W_seg ----
            {
                int rB  = t >> 4;          // 0..15
                int cB  = (t & 15) * 8;    // 0..120
                int din = kt + rB;
                const float4* srcp =
                    reinterpret_cast<const float4*>(&Wp[(size_t)din * DD + n0 + cB]);
                float4 u0 = srcp[0];
                float4 u1 = srcp[1];
                *reinterpret_cast<float4*>(&Bs[rB][cB])     = u0;
                *reinterpret_cast<float4*>(&Bs[rB][cB + 4]) = u1;
            }

            __syncthreads();

            // ---- compute 8x8 per thread ----
#pragma unroll
            for (int kk = 0; kk < BK; kk++) {
                float a[8], b[8];
                *reinterpret_cast<float4*>(&a[0]) = *reinterpret_cast<float4*>(&As[kk][ty * 8]);
                *reinterpret_cast<float4*>(&a[4]) = *reinterpret_cast<float4*>(&As[kk][ty * 8 + 4]);
                *reinterpret_cast<float4*>(&b[0]) = *reinterpret_cast<float4*>(&Bs[kk][tx * 8]);
                *reinterpret_cast<float4*>(&b[4]) = *reinterpret_cast<float4*>(&Bs[kk][tx * 8 + 4]);
#pragma unroll
                for (int i = 0; i < 8; i++)
#pragma unroll
                    for (int j = 0; j < 8; j++)
                        acc[i][j] += a[i] * b[j];
            }
        }
    }

    // ---- epilogue: conditional bias + relu ----
    float bb0[8], bb1[8], bb2[8];
#pragma unroll
    for (int j = 0; j < 8; j++) {
        int col = n0 + tx * 8 + j;   // always < 256
        bb0[j] = b0[col];
        bb1[j] = b1[col];
        bb2[j] = b2[col];
    }
#pragma unroll
    for (int i = 0; i < 8; i++) {
        int lr  = ty * 8 + i;
        int row = m0 + lr;
        if (row >= NN) continue;
        float f0 = s_flg[0][lr], f1 = s_flg[1][lr], f2 = s_flg[2][lr];
        float4 o0, o1;
        float v;
        v = acc[i][0] + f0 * bb0[0] + f1 * bb1[0] + f2 * bb2[0]; o0.x = fmaxf(v, 0.f);
        v = acc[i][1] + f0 * bb0[1] + f1 * bb1[1] + f2 * bb2[1]; o0.y = fmaxf(v, 0.f);
        v = acc[i][2] + f0 * bb0[2] + f1 * bb1[2] + f2 * bb2[2]; o0.z = fmaxf(v, 0.f);
        v = acc[i][3] + f0 * bb0[3] + f1 * bb1[3] + f2 * bb2[3]; o0.w = fmaxf(v, 0.f);
        v = acc[i][4] + f0 * bb0[4] + f1 * bb1[4] + f2 * bb2[4]; o1.x = fmaxf(v, 0.f);
        v = acc[i][5] + f0 * bb0[5] + f1 * bb1[5] + f2 * bb2[5]; o1.y = fmaxf(v, 0.f);
        v = acc[i][6] + f0 * bb0[6] + f1 * bb1[6] + f2 * bb2[6]; o1.z = fmaxf(v, 0.f);
        v = acc[i][7] + f0 * bb0[7] + f1 * bb1[7] + f2 * bb2[7]; o1.w = fmaxf(v, 0.f);
        float* op = &out[(size_t)row * DD + n0 + tx * 8];
        *reinterpret_cast<float4*>(op)     = o0;
        *reinterpret_cast<float4*>(op + 4) = o1;
    }
}

// ---------------- launch ----------------
extern "C" void kernel_launch(void* const* d_in, const int* in_sizes, int n_in,
                              void* d_out, int out_size)
{
    const float* features = (const float*)d_in[0];
    const void*  src0 = d_in[1]; const void* dst0 = d_in[2];
    const void*  src1 = d_in[3]; const void* dst1 = d_in[4];
    const void*  src2 = d_in[5]; const void* dst2 = d_in[6];
    const float* W0 = (const float*)d_in[7];  const float* b0 = (const float*)d_in[8];
    const float* W1 = (const float*)d_in[9];  const float* b1 = (const float*)d_in[10];
    const float* W2 = (const float*)d_in[11]; const float* b2 = (const float*)d_in[12];
    float* out = (float*)d_out;

    detect_kernel<<<1, 32>>>((const int*)src0);

    {
        size_t n4 = (size_t)NN * KTOT / 4;
        int blocks = (int)((n4 + 255) / 256);
        zero_kernel<<<blocks, 256>>>();
    }

    {
        size_t warps = (size_t)EE;                       // one warp per edge
        int blocksx = (int)((warps * 32 + 255) / 256);
        dim3 grid(blocksx, 1, 3);                        // z = relation
        edge_kernel<<<grid, 256>>>(src0, dst0, src1, dst1, src2, dst2, features);
    }

    {
        dim3 grid((NN + BM - 1) / BM, DD / BN);          // (391, 2)
        gemm_kernel<<<grid, 256>>>(W0, b0, W1, b1, W2, b2, out);
    }
}

// round 4
// speedup vs baseline: 1.4740x; 1.4740x over previous
#include <cuda_runtime.h>
#include <cuda_bf16.h>
#include <cstdint>

#define NN   50000
#define EE   500000
#define DD   256
#define KTOT 768            // 3 * DD
#define MPAD 50048          // 391 * 128

// ---------------- scratch (static device globals; no allocation) ----------------
__device__ float          g_agg[(size_t)NN * KTOT];   // fp32 edge-summed features
__device__ float          g_cnt[3 * NN];
__device__ float          g_inv[3 * NN];
__device__ float          g_flg[3 * NN];
__device__ int            g_is64;
__device__ unsigned short g_ah[(size_t)MPAD * KTOT];  // bf16 hi of agg*inv (zero-padded rows)
__device__ unsigned short g_al[(size_t)MPAD * KTOT];  // bf16 lo
__device__ unsigned short g_bh[(size_t)DD * KTOT];    // B[n][k] = W_seg[k][n], bf16 hi
__device__ unsigned short g_bl[(size_t)DD * KTOT];    // bf16 lo

// ================= helpers =================
__device__ __forceinline__ uint32_t smem_u32(const void* p) {
    uint32_t a;
    asm("{ .reg .u64 t; cvta.to.shared.u64 t, %1; cvt.u32.u64 %0, t; }" : "=r"(a) : "l"(p));
    return a;
}
__device__ __forceinline__ uint32_t sw128(uint32_t b) { return b ^ ((b >> 3) & 0x70); }

__device__ __forceinline__ void cp16(uint32_t dst, const void* src) {
    asm volatile("cp.async.cg.shared.global [%0], [%1], 16;" :: "r"(dst), "l"(src));
}
__device__ __forceinline__ void ldm4(uint32_t* r, uint32_t addr) {
    asm volatile("ldmatrix.sync.aligned.m8n8.x4.shared.b16 {%0,%1,%2,%3}, [%4];"
                 : "=r"(r[0]), "=r"(r[1]), "=r"(r[2]), "=r"(r[3]) : "r"(addr));
}
__device__ __forceinline__ void mma_bf16(float* c, const uint32_t* a, const uint32_t* b) {
    asm volatile("mma.sync.aligned.m16n8k16.row.col.f32.bf16.bf16.f32 "
                 "{%0,%1,%2,%3}, {%4,%5,%6,%7}, {%8,%9}, {%0,%1,%2,%3};"
                 : "+f"(c[0]), "+f"(c[1]), "+f"(c[2]), "+f"(c[3])
                 : "r"(a[0]), "r"(a[1]), "r"(a[2]), "r"(a[3]), "r"(b[0]), "r"(b[1]));
}
__device__ __forceinline__ void bsplit(float a, unsigned short& h, unsigned short& l) {
    __nv_bfloat16 hb = __float2bfloat16_rn(a);
    float hf = __bfloat162float(hb);
    __nv_bfloat16 lb = __float2bfloat16_rn(a - hf);
    h = *reinterpret_cast<unsigned short*>(&hb);
    l = *reinterpret_cast<unsigned short*>(&lb);
}

// ================= phase 1: edge aggregation =================
__global__ void detect_kernel(const int* __restrict__ src) {
    if (threadIdx.x == 0 && blockIdx.x == 0) {
        int ok = 1;
#pragma unroll
        for (int i = 0; i < 32; i++)
            if (src[2 * i + 1] != 0) ok = 0;
        g_is64 = ok;
    }
}

__global__ void zero_kernel() {
    size_t i = (size_t)blockIdx.x * blockDim.x + threadIdx.x;
    const size_t n4 = (size_t)NN * KTOT / 4;
    float4 z = make_float4(0.f, 0.f, 0.f, 0.f);
    if (i < n4) reinterpret_cast<float4*>(g_agg)[i] = z;
    if (i < (size_t)(3 * NN) / 4) reinterpret_cast<float4*>(g_cnt)[i] = z;
}

__global__ __launch_bounds__(256) void edge_kernel(
    const void* __restrict__ src0, const void* __restrict__ dst0,
    const void* __restrict__ src1, const void* __restrict__ dst1,
    const void* __restrict__ src2, const void* __restrict__ dst2,
    const float* __restrict__ feat)
{
    int e = (int)(((size_t)blockIdx.x * blockDim.x + threadIdx.x) >> 5);
    if (e >= EE) return;
    const int seg = blockIdx.z;
    const int lane = threadIdx.x & 31;
    const void* src = (seg == 0) ? src0 : ((seg == 1) ? src1 : src2);
    const void* dst = (seg == 0) ? dst0 : ((seg == 1) ? dst1 : dst2);
    int s, d;
    if (g_is64) {
        s = (int)((const long long*)src)[e];
        d = (int)((const long long*)dst)[e];
    } else {
        s = ((const int*)src)[e];
        d = ((const int*)dst)[e];
    }
    if ((unsigned)s >= NN || (unsigned)d >= NN) return;
    const float4* f = reinterpret_cast<const float4*>(feat + (size_t)s * DD);
    float* a = g_agg + (size_t)d * KTOT + (size_t)seg * DD;
    float4 v0 = f[lane];
    float4 v1 = f[lane + 32];
    asm volatile("red.global.add.v4.f32 [%0], {%1,%2,%3,%4};"
                 :: "l"(a + 4 * lane), "f"(v0.x), "f"(v0.y), "f"(v0.z), "f"(v0.w) : "memory");
    asm volatile("red.global.add.v4.f32 [%0], {%1,%2,%3,%4};"
                 :: "l"(a + 4 * (lane + 32)), "f"(v1.x), "f"(v1.y), "f"(v1.z), "f"(v1.w) : "memory");
    if (lane == 0)
        atomicAdd(&g_cnt[seg * NN + d], 1.0f);
}

// ================= phase 2: prep + bf16 split conversion =================
__global__ void prep_kernel() {
    int i = blockIdx.x * blockDim.x + threadIdx.x;
    if (i >= NN) return;
#pragma unroll
    for (int r = 0; r < 3; r++) {
        float c = g_cnt[r * NN + i];
        g_inv[r * NN + i] = (c > 0.f) ? (1.f / c) : 0.f;
        g_flg[r * NN + i] = (c > 0.f) ? 1.f : 0.f;
    }
}

__global__ __launch_bounds__(256) void convertA_kernel() {
    size_t idx = (size_t)blockIdx.x * blockDim.x + threadIdx.x;   // one float4 per thread
    const size_t total = (size_t)MPAD * (KTOT / 4);
    if (idx >= total) return;
    int row = (int)(idx / (KTOT / 4));
    int q   = (int)(idx % (KTOT / 4));
    int seg = q >> 6;
    float4 v = make_float4(0.f, 0.f, 0.f, 0.f);
    float inv = 0.f;
    if (row < NN) {
        v = reinterpret_cast<const float4*>(g_agg)[idx];
        inv = g_inv[seg * NN + row];
    }
    unsigned short h[4], l[4];
    bsplit(v.x * inv, h[0], l[0]);
    bsplit(v.y * inv, h[1], l[1]);
    bsplit(v.z * inv, h[2], l[2]);
    bsplit(v.w * inv, h[3], l[3]);
    uint2 H, L;
    H.x = (uint32_t)h[0] | ((uint32_t)h[1] << 16);
    H.y = (uint32_t)h[2] | ((uint32_t)h[3] << 16);
    L.x = (uint32_t)l[0] | ((uint32_t)l[1] << 16);
    L.y = (uint32_t)l[2] | ((uint32_t)l[3] << 16);
    reinterpret_cast<uint2*>(g_ah)[idx] = H;
    reinterpret_cast<uint2*>(g_al)[idx] = L;
}

__global__ void convertB_kernel(const float* __restrict__ W0,
                                const float* __restrict__ W1,
                                const float* __restrict__ W2) {
    __shared__ float tile[32][33];
    const int seg = blockIdx.z;
    const float* W = (seg == 0) ? W0 : ((seg == 1) ? W1 : W2);
    const int kb = blockIdx.x * 32, nb = blockIdx.y * 32;
    const int tx = threadIdx.x, ty = threadIdx.y;    // 32 x 8
#pragma unroll
    for (int i = 0; i < 32; i += 8)
        tile[ty + i][tx] = W[(size_t)(kb + ty + i) * DD + nb + tx];
    __syncthreads();
#pragma unroll
    for (int i = 0; i < 32; i += 8) {
        int n = nb + ty + i, k = kb + tx;
        unsigned short h, l;
        bsplit(tile[tx][ty + i], h, l);
        g_bh[(size_t)n * KTOT + seg * DD + k] = h;
        g_bl[(size_t)n * KTOT + seg * DD + k] = l;
    }
}

// ================= phase 3: mma.sync bf16 GEMM =================
// CTA tile 128x128, BK=64 bf16 (128B rows, SW128). 3-stage cp.async pipeline.
// stage: AH(16K) AL(16K) BH(16K) BL(16K) = 64KB; 3 stages = 192KB dynamic smem.
#define O_AH 0
#define O_AL 16384
#define O_BH 32768
#define O_BL 49152
#define STG_SZ 65536
#define NSTAGE 3
#define NCHUNK 12
#define SMEM_GEMM (NSTAGE * STG_SZ)

__device__ __forceinline__ void load_chunk(int kc, uint32_t stg, int t, int m0, int n0) {
    const char* ahg = (const char*)g_ah + ((size_t)m0 * KTOT + kc * 64) * 2;
    const char* alg = (const char*)g_al + ((size_t)m0 * KTOT + kc * 64) * 2;
    const char* bhg = (const char*)g_bh + ((size_t)n0 * KTOT + kc * 64) * 2;
    const char* blg = (const char*)g_bl + ((size_t)n0 * KTOT + kc * 64) * 2;
#pragma unroll
    for (int i = t; i < 1024; i += 256) {      // 128 rows x 128B each tile
        int r = i >> 3, j = (i & 7) * 16;
        uint32_t so = sw128(r * 128 + j);
        size_t  go = (size_t)r * (KTOT * 2) + j;
        cp16(stg + O_AH + so, ahg + go);
        cp16(stg + O_AL + so, alg + go);
        cp16(stg + O_BH + so, bhg + go);
        cp16(stg + O_BL + so, blg + go);
    }
    asm volatile("cp.async.commit_group;" ::: "memory");
}

__global__ __launch_bounds__(256) void gemm_mma_kernel(
    const float* __restrict__ b0, const float* __restrict__ b1,
    const float* __restrict__ b2, float* __restrict__ out)
{
    extern __shared__ char smem[];
    const uint32_t sb = smem_u32(smem);
    const int t = threadIdx.x, wid = t >> 5, lane = t & 31;
    const int m0 = blockIdx.x * 128, n0 = blockIdx.y * 128;
    const int wm = wid & 3, wn = wid >> 2;       // warp tile 32x64 in 4x2 grid

    float acc[2][8][4];
#pragma unroll
    for (int i = 0; i < 2; i++)
#pragma unroll
        for (int j = 0; j < 8; j++)
#pragma unroll
            for (int k = 0; k < 4; k++) acc[i][j][k] = 0.f;

    // prologue: 2 stages in flight
    load_chunk(0, sb, t, m0, n0);
    load_chunk(1, sb + STG_SZ, t, m0, n0);

    // precomputed ldmatrix intra-tile offsets (swizzled per k-step inside loop)
    const uint32_t arow = (uint32_t)(wm * 32 + (lane & 15));            // + mf*16
    const uint32_t acol8 = (uint32_t)(lane >> 4);                        // 0/1 -> k +8
    const uint32_t brow = (uint32_t)(wn * 64 + (lane & 7) + ((lane >> 4) & 1) * 8); // + nf2*16
    const uint32_t bcol8 = (uint32_t)((lane >> 3) & 1);

#pragma unroll 1
    for (int c = 0; c < NCHUNK; c++) {
        const uint32_t stg = sb + (uint32_t)(c % NSTAGE) * STG_SZ;

        asm volatile("cp.async.wait_group 1;" ::: "memory");
        __syncthreads();

        if (c + 2 < NCHUNK)
            load_chunk(c + 2, sb + (uint32_t)((c + 2) % NSTAGE) * STG_SZ, t, m0, n0);

#pragma unroll
        for (int ks = 0; ks < 4; ks++) {
            uint32_t ah[2][4], al[2][4], bh[4][4], bl[4][4];
#pragma unroll
            for (int mf = 0; mf < 2; mf++) {
                uint32_t off = sw128((arow + mf * 16) * 128 + (ks * 16 + acol8 * 8) * 2);
                ldm4(ah[mf], stg + O_AH + off);
                ldm4(al[mf], stg + O_AL + off);
            }
#pragma unroll
            for (int nf2 = 0; nf2 < 4; nf2++) {
                uint32_t off = sw128((brow + nf2 * 16) * 128 + (ks * 16 + bcol8 * 8) * 2);
                ldm4(bh[nf2], stg + O_BH + off);
                ldm4(bl[nf2], stg + O_BL + off);
            }
#pragma unroll
            for (int mf = 0; mf < 2; mf++)
#pragma unroll
                for (int nf = 0; nf < 8; nf++) {
                    const uint32_t* bhf = &bh[nf >> 1][2 * (nf & 1)];
                    const uint32_t* blf = &bl[nf >> 1][2 * (nf & 1)];
                    mma_bf16(acc[mf][nf], ah[mf], bhf);   // Ah*Bh
                    mma_bf16(acc[mf][nf], ah[mf], blf);   // Ah*Bl
                    mma_bf16(acc[mf][nf], al[mf], bhf);   // Al*Bh
                }
        }
    }

    // ---- epilogue: bias (flag-gated) + relu, float2 stores ----
    const int gid = lane >> 2, t4 = lane & 3;
    float2 bb0[8], bb1[8], bb2[8];
#pragma unroll
    for (int nf = 0; nf < 8; nf++) {
        int col = n0 + wn * 64 + nf * 8 + t4 * 2;
        bb0[nf] = *reinterpret_cast<const float2*>(b0 + col);
        bb1[nf] = *reinterpret_cast<const float2*>(b1 + col);
        bb2[nf] = *reinterpret_cast<const float2*>(b2 + col);
    }
#pragma unroll
    for (int mf = 0; mf < 2; mf++) {
#pragma unroll
        for (int half = 0; half < 2; half++) {
            int row = m0 + wm * 32 + mf * 16 + gid + half * 8;
            if (row >= NN) continue;
            float f0 = g_flg[row], f1 = g_flg[NN + row], f2 = g_flg[2 * NN + row];
#pragma unroll
            for (int nf = 0; nf < 8; nf++) {
                int col = n0 + wn * 64 + nf * 8 + t4 * 2;
                float2 o;
                o.x = fmaxf(acc[mf][nf][2 * half]     + f0 * bb0[nf].x + f1 * bb1[nf].x + f2 * bb2[nf].x, 0.f);
                o.y = fmaxf(acc[mf][nf][2 * half + 1] + f0 * bb0[nf].y + f1 * bb1[nf].y + f2 * bb2[nf].y, 0.f);
                *reinterpret_cast<float2*>(out + (size_t)row * DD + col) = o;
            }
        }
    }
}

// ================= launch =================
extern "C" void kernel_launch(void* const* d_in, const int* in_sizes, int n_in,
                              void* d_out, int out_size)
{
    const float* features = (const float*)d_in[0];
    const void*  src0 = d_in[1]; const void* dst0 = d_in[2];
    const void*  src1 = d_in[3]; const void* dst1 = d_in[4];
    const void*  src2 = d_in[5]; const void* dst2 = d_in[6];
    const float* W0 = (const float*)d_in[7];  const float* b0 = (const float*)d_in[8];
    const float* W1 = (const float*)d_in[9];  const float* b1 = (const float*)d_in[10];
    const float* W2 = (const float*)d_in[11]; const float* b2 = (const float*)d_in[12];
    float* out = (float*)d_out;

    cudaFuncSetAttribute(gemm_mma_kernel, cudaFuncAttributeMaxDynamicSharedMemorySize,
                         SMEM_GEMM);

    detect_kernel<<<1, 32>>>((const int*)src0);

    {
        size_t n4 = (size_t)NN * KTOT / 4;
        int blocks = (int)((n4 + 255) / 256);
        zero_kernel<<<blocks, 256>>>();
    }
    {
        int blocksx = (int)(((size_t)EE * 32 + 255) / 256);
        dim3 grid(blocksx, 1, 3);
        edge_kernel<<<grid, 256>>>(src0, dst0, src1, dst1, src2, dst2, features);
    }
    prep_kernel<<<(NN + 255) / 256, 256>>>();
    {
        size_t total = (size_t)MPAD * (KTOT / 4);
        convertA_kernel<<<(int)((total + 255) / 256), 256>>>();
    }
    {
        dim3 grid(DD / 32, DD / 32, 3);   // (8, 8, 3)
        convertB_kernel<<<grid, dim3(32, 8)>>>(W0, W1, W2);
    }
    {
        dim3 grid(MPAD / 128, 2);         // (391, 2)
        gemm_mma_kernel<<<grid, 256, SMEM_GEMM>>>(b0, b1, b2, out);
    }
}

// round 5
// speedup vs baseline: 2.5447x; 1.7264x over previous
#include <cuda_runtime.h>
#include <cuda_bf16.h>
#include <cstdint>

#define NN   50000
#define EE   500000
#define DD   256
#define KTOT 768            // 3 * DD
#define MPAD 50048          // 391 * 128
#define NSEG3 (3 * NN)

// ---------------- scratch (static device globals; zero-initialized at load) ----------------
__device__ int            g_is64;
__device__ int            g_icnt[NSEG3];               // in-degree per (seg,node)
__device__ int            g_cur[NSEG3];                // scatter cursors
__device__ int            g_off[NSEG3];                // block-local exclusive offsets
__device__ int            g_bsum[1024];                // per-block sums
__device__ int            g_bsumx[1024];               // exclusive block prefix
__device__ int            g_csr[3 * EE];               // src indices grouped by (seg,dst)
__device__ float          g_flg[NSEG3];                // seg-major presence flags
__device__ unsigned short g_ah[(size_t)MPAD * KTOT];   // bf16 hi of mean-agg (rows>=NN stay 0)
__device__ unsigned short g_al[(size_t)MPAD * KTOT];   // bf16 lo
__device__ unsigned short g_bh[(size_t)DD * KTOT];     // B[n][k] = W_seg[k][n], bf16 hi
__device__ unsigned short g_bl[(size_t)DD * KTOT];     // bf16 lo

// ================= helpers =================
__device__ __forceinline__ uint32_t smem_u32(const void* p) {
    uint32_t a;
    asm("{ .reg .u64 t; cvta.to.shared.u64 t, %1; cvt.u32.u64 %0, t; }" : "=r"(a) : "l"(p));
    return a;
}
__device__ __forceinline__ uint32_t sw128(uint32_t b) { return b ^ ((b >> 3) & 0x70); }

__device__ __forceinline__ void cp16(uint32_t dst, const void* src) {
    asm volatile("cp.async.cg.shared.global [%0], [%1], 16;" :: "r"(dst), "l"(src));
}
__device__ __forceinline__ void ldm4(uint32_t* r, uint32_t addr) {
    asm volatile("ldmatrix.sync.aligned.m8n8.x4.shared.b16 {%0,%1,%2,%3}, [%4];"
                 : "=r"(r[0]), "=r"(r[1]), "=r"(r[2]), "=r"(r[3]) : "r"(addr));
}
__device__ __forceinline__ void mma_bf16(float* c, const uint32_t* a, const uint32_t* b) {
    asm volatile("mma.sync.aligned.m16n8k16.row.col.f32.bf16.bf16.f32 "
                 "{%0,%1,%2,%3}, {%4,%5,%6,%7}, {%8,%9}, {%0,%1,%2,%3};"
                 : "+f"(c[0]), "+f"(c[1]), "+f"(c[2]), "+f"(c[3])
                 : "r"(a[0]), "r"(a[1]), "r"(a[2]), "r"(a[3]), "r"(b[0]), "r"(b[1]));
}
__device__ __forceinline__ void bsplit(float a, unsigned short& h, unsigned short& l) {
    __nv_bfloat16 hb = __float2bfloat16_rn(a);
    float hf = __bfloat162float(hb);
    __nv_bfloat16 lb = __float2bfloat16_rn(a - hf);
    h = *reinterpret_cast<unsigned short*>(&hb);
    l = *reinterpret_cast<unsigned short*>(&lb);
}

// ================= phase 0: dtype detect + zero counters =================
__global__ void detect_kernel(const int* __restrict__ src) {
    if (threadIdx.x == 0 && blockIdx.x == 0) {
        int ok = 1;
#pragma unroll
        for (int i = 0; i < 32; i++)
            if (src[2 * i + 1] != 0) ok = 0;
        g_is64 = ok;
    }
}

__global__ void zero_cnt_kernel() {
    int i = blockIdx.x * blockDim.x + threadIdx.x;
    if (i < NSEG3) { g_icnt[i] = 0; g_cur[i] = 0; }
}

// ================= phase 1: CSR build =================
__global__ __launch_bounds__(256) void hist_kernel(
    const void* __restrict__ dst0, const void* __restrict__ dst1,
    const void* __restrict__ dst2)
{
    int e = blockIdx.x * blockDim.x + threadIdx.x;
    if (e >= EE) return;
    const int seg = blockIdx.z;
    const void* dst = (seg == 0) ? dst0 : ((seg == 1) ? dst1 : dst2);
    int d = g_is64 ? (int)((const long long*)dst)[e] : ((const int*)dst)[e];
    if ((unsigned)d >= NN) return;
    atomicAdd(&g_icnt[seg * NN + d], 1);
}

// block-level exclusive scan of g_icnt (256/block) -> g_off, block totals -> g_bsum
__global__ __launch_bounds__(256) void scan1_kernel() {
    __shared__ int sh[256];
    int t = threadIdx.x;
    int i = blockIdx.x * 256 + t;
    int v = (i < NSEG3) ? g_icnt[i] : 0;
    sh[t] = v;
    __syncthreads();
    int acc = v;
#pragma unroll
    for (int ofs = 1; ofs < 256; ofs <<= 1) {
        int o = (t >= ofs) ? sh[t - ofs] : 0;
        __syncthreads();
        acc += o;
        sh[t] = acc;
        __syncthreads();
    }
    if (i < NSEG3) g_off[i] = acc - v;          // exclusive within block
    if (t == 255) g_bsum[blockIdx.x] = acc;     // block total
}

// exclusive scan of block sums (<=1024)
__global__ __launch_bounds__(1024) void scan2_kernel(int nblocks) {
    __shared__ int sh[1024];
    int t = threadIdx.x;
    int v = (t < nblocks) ? g_bsum[t] : 0;
    sh[t] = v;
    __syncthreads();
    int acc = v;
#pragma unroll
    for (int ofs = 1; ofs < 1024; ofs <<= 1) {
        int o = (t >= ofs) ? sh[t - ofs] : 0;
        __syncthreads();
        acc += o;
        sh[t] = acc;
        __syncthreads();
    }
    g_bsumx[t] = acc - v;
}

__global__ __launch_bounds__(256) void scatter_kernel(
    const void* __restrict__ src0, const void* __restrict__ dst0,
    const void* __restrict__ src1, const void* __restrict__ dst1,
    const void* __restrict__ src2, const void* __restrict__ dst2)
{
    int e = blockIdx.x * blockDim.x + threadIdx.x;
    if (e >= EE) return;
    const int seg = blockIdx.z;
    const void* src = (seg == 0) ? src0 : ((seg == 1) ? src1 : src2);
    const void* dst = (seg == 0) ? dst0 : ((seg == 1) ? dst1 : dst2);
    int s, d;
    if (g_is64) {
        s = (int)((const long long*)src)[e];
        d = (int)((const long long*)dst)[e];
    } else {
        s = ((const int*)src)[e];
        d = ((const int*)dst)[e];
    }
    if ((unsigned)s >= NN || (unsigned)d >= NN) return;
    int idx  = seg * NN + d;
    int base = g_off[idx] + g_bsumx[idx >> 8];
    int pos  = base + atomicAdd(&g_cur[idx], 1);
    g_csr[pos] = s;
}

// ================= phase 2: fused gather + mean + bf16 split =================
// one warp per (seg, node): sum in-neighbor feature rows in regs, scale by 1/deg,
// split to bf16 hi/lo, write g_ah/g_al directly. Writes g_flg.
__global__ __launch_bounds__(256) void node_gather_kernel(const float* __restrict__ feat)
{
    int gw = (blockIdx.x * blockDim.x + threadIdx.x) >> 5;   // global warp id
    if (gw >= NSEG3) return;
    const int lane = threadIdx.x & 31;
    const int seg  = gw / NN;
    const int node = gw - seg * NN;

    const int deg  = g_icnt[gw];
    const int base = g_off[gw] + g_bsumx[gw >> 8];

    // lane covers floats [4*lane, 4*lane+4) and [128+4*lane, +4)
    float4 a0 = make_float4(0.f, 0.f, 0.f, 0.f);
    float4 a1 = make_float4(0.f, 0.f, 0.f, 0.f);

    int p = 0;
    for (; p + 1 < deg; p += 2) {                 // 2 edges in flight -> 4 LDG.128/lane
        int s0 = g_csr[base + p];
        int s1 = g_csr[base + p + 1];
        const float4* f0 = reinterpret_cast<const float4*>(feat + (size_t)s0 * DD);
        const float4* f1 = reinterpret_cast<const float4*>(feat + (size_t)s1 * DD);
        float4 u0 = __ldg(&f0[lane]);
        float4 u1 = __ldg(&f0[lane + 32]);
        float4 v0 = __ldg(&f1[lane]);
        float4 v1 = __ldg(&f1[lane + 32]);
        a0.x += u0.x + v0.x; a0.y += u0.y + v0.y; a0.z += u0.z + v0.z; a0.w += u0.w + v0.w;
        a1.x += u1.x + v1.x; a1.y += u1.y + v1.y; a1.z += u1.z + v1.z; a1.w += u1.w + v1.w;
    }
    if (p < deg) {
        int s0 = g_csr[base + p];
        const float4* f0 = reinterpret_cast<const float4*>(feat + (size_t)s0 * DD);
        float4 u0 = __ldg(&f0[lane]);
        float4 u1 = __ldg(&f0[lane + 32]);
        a0.x += u0.x; a0.y += u0.y; a0.z += u0.z; a0.w += u0.w;
        a1.x += u1.x; a1.y += u1.y; a1.z += u1.z; a1.w += u1.w;
    }

    const float inv = (deg > 0) ? (1.f / (float)deg) : 0.f;
    unsigned short h[8], l[8];
    bsplit(a0.x * inv, h[0], l[0]);
    bsplit(a0.y * inv, h[1], l[1]);
    bsplit(a0.z * inv, h[2], l[2]);
    bsplit(a0.w * inv, h[3], l[3]);
    bsplit(a1.x * inv, h[4], l[4]);
    bsplit(a1.y * inv, h[5], l[5]);
    bsplit(a1.z * inv, h[6], l[6]);
    bsplit(a1.w * inv, h[7], l[7]);

    unsigned short* rh = g_ah + (size_t)node * KTOT + seg * DD;
    unsigned short* rl = g_al + (size_t)node * KTOT + seg * DD;
    uint2 H0, H1, L0, L1;
    H0.x = (uint32_t)h[0] | ((uint32_t)h[1] << 16);
    H0.y = (uint32_t)h[2] | ((uint32_t)h[3] << 16);
    H1.x = (uint32_t)h[4] | ((uint32_t)h[5] << 16);
    H1.y = (uint32_t)h[6] | ((uint32_t)h[7] << 16);
    L0.x = (uint32_t)l[0] | ((uint32_t)l[1] << 16);
    L0.y = (uint32_t)l[2] | ((uint32_t)l[3] << 16);
    L1.x = (uint32_t)l[4] | ((uint32_t)l[5] << 16);
    L1.y = (uint32_t)l[6] | ((uint32_t)l[7] << 16);
    *reinterpret_cast<uint2*>(rh + 4 * lane)       = H0;
    *reinterpret_cast<uint2*>(rh + 128 + 4 * lane) = H1;
    *reinterpret_cast<uint2*>(rl + 4 * lane)       = L0;
    *reinterpret_cast<uint2*>(rl + 128 + 4 * lane) = L1;
    if (lane == 0)
        g_flg[gw] = (deg > 0) ? 1.f : 0.f;
}

// ================= phase 2b: B transpose + split =================
__global__ void convertB_kernel(const float* __restrict__ W0,
                                const float* __restrict__ W1,
                                const float* __restrict__ W2) {
    __shared__ float tile[32][33];
    const int seg = blockIdx.z;
    const float* W = (seg == 0) ? W0 : ((seg == 1) ? W1 : W2);
    const int kb = blockIdx.x * 32, nb = blockIdx.y * 32;
    const int tx = threadIdx.x, ty = threadIdx.y;    // 32 x 8
#pragma unroll
    for (int i = 0; i < 32; i += 8)
        tile[ty + i][tx] = W[(size_t)(kb + ty + i) * DD + nb + tx];
    __syncthreads();
#pragma unroll
    for (int i = 0; i < 32; i += 8) {
        int n = nb + ty + i, k = kb + tx;
        unsigned short h, l;
        bsplit(tile[tx][ty + i], h, l);
        g_bh[(size_t)n * KTOT + seg * DD + k] = h;
        g_bl[(size_t)n * KTOT + seg * DD + k] = l;
    }
}

// ================= phase 3: mma.sync bf16 GEMM (unchanged from R4 pass) =================
#define O_AH 0
#define O_AL 16384
#define O_BH 32768
#define O_BL 49152
#define STG_SZ 65536
#define NSTAGE 3
#define NCHUNK 12
#define SMEM_GEMM (NSTAGE * STG_SZ)

__device__ __forceinline__ void load_chunk(int kc, uint32_t stg, int t, int m0, int n0) {
    const char* ahg = (const char*)g_ah + ((size_t)m0 * KTOT + kc * 64) * 2;
    const char* alg = (const char*)g_al + ((size_t)m0 * KTOT + kc * 64) * 2;
    const char* bhg = (const char*)g_bh + ((size_t)n0 * KTOT + kc * 64) * 2;
    const char* blg = (const char*)g_bl + ((size_t)n0 * KTOT + kc * 64) * 2;
#pragma unroll
    for (int i = t; i < 1024; i += 256) {
        int r = i >> 3, j = (i & 7) * 16;
        uint32_t so = sw128(r * 128 + j);
        size_t  go = (size_t)r * (KTOT * 2) + j;
        cp16(stg + O_AH + so, ahg + go);
        cp16(stg + O_AL + so, alg + go);
        cp16(stg + O_BH + so, bhg + go);
        cp16(stg + O_BL + so, blg + go);
    }
    asm volatile("cp.async.commit_group;" ::: "memory");
}

__global__ __launch_bounds__(256) void gemm_mma_kernel(
    const float* __restrict__ b0, const float* __restrict__ b1,
    const float* __restrict__ b2, float* __restrict__ out)
{
    extern __shared__ char smem[];
    const uint32_t sb = smem_u32(smem);
    const int t = threadIdx.x, wid = t >> 5, lane = t & 31;
    const int m0 = blockIdx.x * 128, n0 = blockIdx.y * 128;
    const int wm = wid & 3, wn = wid >> 2;

    float acc[2][8][4];
#pragma unroll
    for (int i = 0; i < 2; i++)
#pragma unroll
        for (int j = 0; j < 8; j++)
#pragma unroll
            for (int k = 0; k < 4; k++) acc[i][j][k] = 0.f;

    load_chunk(0, sb, t, m0, n0);
    load_chunk(1, sb + STG_SZ, t, m0, n0);

    const uint32_t arow = (uint32_t)(wm * 32 + (lane & 15));
    const uint32_t acol8 = (uint32_t)(lane >> 4);
    const uint32_t brow = (uint32_t)(wn * 64 + (lane & 7) + ((lane >> 4) & 1) * 8);
    const uint32_t bcol8 = (uint32_t)((lane >> 3) & 1);

#pragma unroll 1
    for (int c = 0; c < NCHUNK; c++) {
        const uint32_t stg = sb + (uint32_t)(c % NSTAGE) * STG_SZ;

        asm volatile("cp.async.wait_group 1;" ::: "memory");
        __syncthreads();

        if (c + 2 < NCHUNK)
            load_chunk(c + 2, sb + (uint32_t)((c + 2) % NSTAGE) * STG_SZ, t, m0, n0);

#pragma unroll
        for (int ks = 0; ks < 4; ks++) {
            uint32_t ah[2][4], al[2][4], bh[4][4], bl[4][4];
#pragma unroll
            for (int mf = 0; mf < 2; mf++) {
                uint32_t off = sw128((arow + mf * 16) * 128 + (ks * 16 + acol8 * 8) * 2);
                ldm4(ah[mf], stg + O_AH + off);
                ldm4(al[mf], stg + O_AL + off);
            }
#pragma unroll
            for (int nf2 = 0; nf2 < 4; nf2++) {
                uint32_t off = sw128((brow + nf2 * 16) * 128 + (ks * 16 + bcol8 * 8) * 2);
                ldm4(bh[nf2], stg + O_BH + off);
                ldm4(bl[nf2], stg + O_BL + off);
            }
#pragma unroll
            for (int mf = 0; mf < 2; mf++)
#pragma unroll
                for (int nf = 0; nf < 8; nf++) {
                    const uint32_t* bhf = &bh[nf >> 1][2 * (nf & 1)];
                    const uint32_t* blf = &bl[nf >> 1][2 * (nf & 1)];
                    mma_bf16(acc[mf][nf], ah[mf], bhf);
                    mma_bf16(acc[mf][nf], ah[mf], blf);
                    mma_bf16(acc[mf][nf], al[mf], bhf);
                }
        }
    }

    const int gid = lane >> 2, t4 = lane & 3;
    float2 bb0[8], bb1[8], bb2[8];
#pragma unroll
    for (int nf = 0; nf < 8; nf++) {
        int col = n0 + wn * 64 + nf * 8 + t4 * 2;
        bb0[nf] = *reinterpret_cast<const float2*>(b0 + col);
        bb1[nf] = *reinterpret_cast<const float2*>(b1 + col);
        bb2[nf] = *reinterpret_cast<const float2*>(b2 + col);
    }
#pragma unroll
    for (int mf = 0; mf < 2; mf++) {
#pragma unroll
        for (int half = 0; half < 2; half++) {
            int row = m0 + wm * 32 + mf * 16 + gid + half * 8;
            if (row >= NN) continue;
            float f0 = g_flg[row], f1 = g_flg[NN + row], f2 = g_flg[2 * NN + row];
#pragma unroll
            for (int nf = 0; nf < 8; nf++) {
                int col = n0 + wn * 64 + nf * 8 + t4 * 2;
                float2 o;
                o.x = fmaxf(acc[mf][nf][2 * half]     + f0 * bb0[nf].x + f1 * bb1[nf].x + f2 * bb2[nf].x, 0.f);
                o.y = fmaxf(acc[mf][nf][2 * half + 1] + f0 * bb0[nf].y + f1 * bb1[nf].y + f2 * bb2[nf].y, 0.f);
                *reinterpret_cast<float2*>(out + (size_t)row * DD + col) = o;
            }
        }
    }
}

// ================= launch =================
extern "C" void kernel_launch(void* const* d_in, const int* in_sizes, int n_in,
                              void* d_out, int out_size)
{
    const float* features = (const float*)d_in[0];
    const void*  src0 = d_in[1]; const void* dst0 = d_in[2];
    const void*  src1 = d_in[3]; const void* dst1 = d_in[4];
    const void*  src2 = d_in[5]; const void* dst2 = d_in[6];
    const float* W0 = (const float*)d_in[7];  const float* b0 = (const float*)d_in[8];
    const float* W1 = (const float*)d_in[9];  const float* b1 = (const float*)d_in[10];
    const float* W2 = (const float*)d_in[11]; const float* b2 = (const float*)d_in[12];
    float* out = (float*)d_out;

    cudaFuncSetAttribute(gemm_mma_kernel, cudaFuncAttributeMaxDynamicSharedMemorySize,
                         SMEM_GEMM);

    const int nScanBlocks = (NSEG3 + 255) / 256;   // 586

    detect_kernel<<<1, 32>>>((const int*)src0);
    zero_cnt_kernel<<<(NSEG3 + 255) / 256, 256>>>();

    {
        dim3 grid((EE + 255) / 256, 1, 3);
        hist_kernel<<<grid, 256>>>(dst0, dst1, dst2);
    }
    scan1_kernel<<<nScanBlocks, 256>>>();
    scan2_kernel<<<1, 1024>>>(nScanBlocks);
    {
        dim3 grid((EE + 255) / 256, 1, 3);
        scatter_kernel<<<grid, 256>>>(src0, dst0, src1, dst1, src2, dst2);
    }
    {
        int blocks = (NSEG3 * 32 + 255) / 256;     // one warp per (seg,node)
        node_gather_kernel<<<blocks, 256>>>(features);
    }
    {
        dim3 grid(DD / 32, DD / 32, 3);
        convertB_kernel<<<grid, dim3(32, 8)>>>(W0, W1, W2);
    }
    {
        dim3 grid(MPAD / 128, 2);
        gemm_mma_kernel<<<grid, 256, SMEM_GEMM>>>(b0, b1, b2, out);
    }
}

// round 6
// speedup vs baseline: 2.6084x; 1.0250x over previous
#include <cuda_runtime.h>
#include <cuda_bf16.h>
#include <cstdint>

#define NN   50000
#define EE   500000
#define DD   256
#define KTOT 768            // 3 * DD
#define MPAD 50048          // 391 * 128
#define NSEG3 (3 * NN)

// ---------------- scratch (static device globals; zero-initialized at load) ----------------
__device__ int            g_is64;
__device__ int            g_icnt[NSEG3];               // in-degree per (seg,node)
__device__ int            g_cur[NSEG3];                // scatter cursors
__device__ int            g_off[NSEG3];                // block-local exclusive offsets
__device__ int            g_bsum[1024];                // per-block sums
__device__ int            g_bsumx[1024];               // exclusive block prefix
__device__ int            g_csr[3 * EE];               // src indices grouped by (seg,dst)
__device__ float          g_flg[NSEG3];                // seg-major presence flags
__device__ unsigned short g_ah[(size_t)MPAD * KTOT];   // bf16 hi of mean-agg (rows>=NN stay 0)
__device__ unsigned short g_al[(size_t)MPAD * KTOT];   // bf16 lo
__device__ unsigned short g_bh[(size_t)DD * KTOT];     // B[n][k] = W_seg[k][n], bf16 hi
__device__ unsigned short g_bl[(size_t)DD * KTOT];     // bf16 lo

// ================= helpers =================
__device__ __forceinline__ uint32_t smem_u32(const void* p) {
    uint32_t a;
    asm("{ .reg .u64 t; cvta.to.shared.u64 t, %1; cvt.u32.u64 %0, t; }" : "=r"(a) : "l"(p));
    return a;
}
__device__ __forceinline__ uint32_t sw128(uint32_t b) { return b ^ ((b >> 3) & 0x70); }

__device__ __forceinline__ void cp16(uint32_t dst, const void* src) {
    asm volatile("cp.async.cg.shared.global [%0], [%1], 16;" :: "r"(dst), "l"(src));
}
__device__ __forceinline__ void ldm4(uint32_t* r, uint32_t addr) {
    asm volatile("ldmatrix.sync.aligned.m8n8.x4.shared.b16 {%0,%1,%2,%3}, [%4];"
                 : "=r"(r[0]), "=r"(r[1]), "=r"(r[2]), "=r"(r[3]) : "r"(addr));
}
__device__ __forceinline__ void mma_bf16(float* c, const uint32_t* a, const uint32_t* b) {
    asm volatile("mma.sync.aligned.m16n8k16.row.col.f32.bf16.bf16.f32 "
                 "{%0,%1,%2,%3}, {%4,%5,%6,%7}, {%8,%9}, {%0,%1,%2,%3};"
                 : "+f"(c[0]), "+f"(c[1]), "+f"(c[2]), "+f"(c[3])
                 : "r"(a[0]), "r"(a[1]), "r"(a[2]), "r"(a[3]), "r"(b[0]), "r"(b[1]));
}
__device__ __forceinline__ void bsplit(float a, unsigned short& h, unsigned short& l) {
    __nv_bfloat16 hb = __float2bfloat16_rn(a);
    float hf = __bfloat162float(hb);
    __nv_bfloat16 lb = __float2bfloat16_rn(a - hf);
    h = *reinterpret_cast<unsigned short*>(&hb);
    l = *reinterpret_cast<unsigned short*>(&lb);
}

// ================= phase 0: dtype detect + zero counters =================
__global__ void detect_kernel(const int* __restrict__ src) {
    if (threadIdx.x == 0 && blockIdx.x == 0) {
        int ok = 1;
#pragma unroll
        for (int i = 0; i < 32; i++)
            if (src[2 * i + 1] != 0) ok = 0;
        g_is64 = ok;
    }
}

__global__ void zero_cnt_kernel() {
    int i = blockIdx.x * blockDim.x + threadIdx.x;
    if (i < NSEG3) { g_icnt[i] = 0; g_cur[i] = 0; }
}

// ================= phase 1: CSR build =================
__global__ __launch_bounds__(256) void hist_kernel(
    const void* __restrict__ dst0, const void* __restrict__ dst1,
    const void* __restrict__ dst2)
{
    int e = blockIdx.x * blockDim.x + threadIdx.x;
    if (e >= EE) return;
    const int seg = blockIdx.z;
    const void* dst = (seg == 0) ? dst0 : ((seg == 1) ? dst1 : dst2);
    int d = g_is64 ? (int)((const long long*)dst)[e] : ((const int*)dst)[e];
    if ((unsigned)d >= NN) return;
    atomicAdd(&g_icnt[seg * NN + d], 1);
}

__global__ __launch_bounds__(256) void scan1_kernel() {
    __shared__ int sh[256];
    int t = threadIdx.x;
    int i = blockIdx.x * 256 + t;
    int v = (i < NSEG3) ? g_icnt[i] : 0;
    sh[t] = v;
    __syncthreads();
    int acc = v;
#pragma unroll
    for (int ofs = 1; ofs < 256; ofs <<= 1) {
        int o = (t >= ofs) ? sh[t - ofs] : 0;
        __syncthreads();
        acc += o;
        sh[t] = acc;
        __syncthreads();
    }
    if (i < NSEG3) g_off[i] = acc - v;
    if (t == 255) g_bsum[blockIdx.x] = acc;
}

__global__ __launch_bounds__(1024) void scan2_kernel(int nblocks) {
    __shared__ int sh[1024];
    int t = threadIdx.x;
    int v = (t < nblocks) ? g_bsum[t] : 0;
    sh[t] = v;
    __syncthreads();
    int acc = v;
#pragma unroll
    for (int ofs = 1; ofs < 1024; ofs <<= 1) {
        int o = (t >= ofs) ? sh[t - ofs] : 0;
        __syncthreads();
        acc += o;
        sh[t] = acc;
        __syncthreads();
    }
    g_bsumx[t] = acc - v;
}

__global__ __launch_bounds__(256) void scatter_kernel(
    const void* __restrict__ src0, const void* __restrict__ dst0,
    const void* __restrict__ src1, const void* __restrict__ dst1,
    const void* __restrict__ src2, const void* __restrict__ dst2)
{
    int e = blockIdx.x * blockDim.x + threadIdx.x;
    if (e >= EE) return;
    const int seg = blockIdx.z;
    const void* src = (seg == 0) ? src0 : ((seg == 1) ? src1 : src2);
    const void* dst = (seg == 0) ? dst0 : ((seg == 1) ? dst1 : dst2);
    int s, d;
    if (g_is64) {
        s = (int)((const long long*)src)[e];
        d = (int)((const long long*)dst)[e];
    } else {
        s = ((const int*)src)[e];
        d = ((const int*)dst)[e];
    }
    if ((unsigned)s >= NN || (unsigned)d >= NN) return;
    int idx  = seg * NN + d;
    int base = g_off[idx] + g_bsumx[idx >> 8];
    int pos  = base + atomicAdd(&g_cur[idx], 1);
    g_csr[pos] = s;
}

// ================= phase 2: fused gather + mean + bf16 split =================
__global__ __launch_bounds__(256) void node_gather_kernel(const float* __restrict__ feat)
{
    int gw = (blockIdx.x * blockDim.x + threadIdx.x) >> 5;   // global warp id
    if (gw >= NSEG3) return;
    const int lane = threadIdx.x & 31;
    const int seg  = gw / NN;
    const int node = gw - seg * NN;

    const int deg  = g_icnt[gw];
    const int base = g_off[gw] + g_bsumx[gw >> 8];

    float4 a0 = make_float4(0.f, 0.f, 0.f, 0.f);
    float4 a1 = make_float4(0.f, 0.f, 0.f, 0.f);

    int p = 0;
    for (; p + 1 < deg; p += 2) {
        int s0 = g_csr[base + p];
        int s1 = g_csr[base + p + 1];
        const float4* f0 = reinterpret_cast<const float4*>(feat + (size_t)s0 * DD);
        const float4* f1 = reinterpret_cast<const float4*>(feat + (size_t)s1 * DD);
        float4 u0 = __ldg(&f0[lane]);
        float4 u1 = __ldg(&f0[lane + 32]);
        float4 v0 = __ldg(&f1[lane]);
        float4 v1 = __ldg(&f1[lane + 32]);
        a0.x += u0.x + v0.x; a0.y += u0.y + v0.y; a0.z += u0.z + v0.z; a0.w += u0.w + v0.w;
        a1.x += u1.x + v1.x; a1.y += u1.y + v1.y; a1.z += u1.z + v1.z; a1.w += u1.w + v1.w;
    }
    if (p < deg) {
        int s0 = g_csr[base + p];
        const float4* f0 = reinterpret_cast<const float4*>(feat + (size_t)s0 * DD);
        float4 u0 = __ldg(&f0[lane]);
        float4 u1 = __ldg(&f0[lane + 32]);
        a0.x += u0.x; a0.y += u0.y; a0.z += u0.z; a0.w += u0.w;
        a1.x += u1.x; a1.y += u1.y; a1.z += u1.z; a1.w += u1.w;
    }

    const float inv = (deg > 0) ? (1.f / (float)deg) : 0.f;
    unsigned short h[8], l[8];
    bsplit(a0.x * inv, h[0], l[0]);
    bsplit(a0.y * inv, h[1], l[1]);
    bsplit(a0.z * inv, h[2], l[2]);
    bsplit(a0.w * inv, h[3], l[3]);
    bsplit(a1.x * inv, h[4], l[4]);
    bsplit(a1.y * inv, h[5], l[5]);
    bsplit(a1.z * inv, h[6], l[6]);
    bsplit(a1.w * inv, h[7], l[7]);

    unsigned short* rh = g_ah + (size_t)node * KTOT + seg * DD;
    unsigned short* rl = g_al + (size_t)node * KTOT + seg * DD;
    uint2 H0, H1, L0, L1;
    H0.x = (uint32_t)h[0] | ((uint32_t)h[1] << 16);
    H0.y = (uint32_t)h[2] | ((uint32_t)h[3] << 16);
    H1.x = (uint32_t)h[4] | ((uint32_t)h[5] << 16);
    H1.y = (uint32_t)h[6] | ((uint32_t)h[7] << 16);
    L0.x = (uint32_t)l[0] | ((uint32_t)l[1] << 16);
    L0.y = (uint32_t)l[2] | ((uint32_t)l[3] << 16);
    L1.x = (uint32_t)l[4] | ((uint32_t)l[5] << 16);
    L1.y = (uint32_t)l[6] | ((uint32_t)l[7] << 16);
    *reinterpret_cast<uint2*>(rh + 4 * lane)       = H0;
    *reinterpret_cast<uint2*>(rh + 128 + 4 * lane) = H1;
    *reinterpret_cast<uint2*>(rl + 4 * lane)       = L0;
    *reinterpret_cast<uint2*>(rl + 128 + 4 * lane) = L1;
    if (lane == 0)
        g_flg[gw] = (deg > 0) ? 1.f : 0.f;
}

// ================= phase 2b: B transpose + split =================
__global__ void convertB_kernel(const float* __restrict__ W0,
                                const float* __restrict__ W1,
                                const float* __restrict__ W2) {
    __shared__ float tile[32][33];
    const int seg = blockIdx.z;
    const float* W = (seg == 0) ? W0 : ((seg == 1) ? W1 : W2);
    const int kb = blockIdx.x * 32, nb = blockIdx.y * 32;
    const int tx = threadIdx.x, ty = threadIdx.y;    // 32 x 8
#pragma unroll
    for (int i = 0; i < 32; i += 8)
        tile[ty + i][tx] = W[(size_t)(kb + ty + i) * DD + nb + tx];
    __syncthreads();
#pragma unroll
    for (int i = 0; i < 32; i += 8) {
        int n = nb + ty + i, k = kb + tx;
        unsigned short h, l;
        bsplit(tile[tx][ty + i], h, l);
        g_bh[(size_t)n * KTOT + seg * DD + k] = h;
        g_bl[(size_t)n * KTOT + seg * DD + k] = l;
    }
}

// ================= phase 3: mma.sync bf16 GEMM =================
// CTA tile 128(M) x 256(N, full), BK=64. Warp tile 64x64, 8 warps in 2(M) x 4(N).
// 2-stage cp.async pipeline. Stage: AH(16K) AL(16K) BH(32K) BL(32K) = 96KB; 2 stages = 192KB.
#define O_AH 0
#define O_AL 16384
#define O_BH 32768
#define O_BL 65536
#define STG_SZ 98304
#define NSTAGE 2
#define NCHUNK 12
#define SMEM_GEMM (NSTAGE * STG_SZ)

__device__ __forceinline__ void load_chunk(int kc, uint32_t stg, int t, int m0) {
    const char* ahg = (const char*)g_ah + ((size_t)m0 * KTOT + kc * 64) * 2;
    const char* alg = (const char*)g_al + ((size_t)m0 * KTOT + kc * 64) * 2;
    const char* bhg = (const char*)g_bh + ((size_t)kc * 64) * 2;
    const char* blg = (const char*)g_bl + ((size_t)kc * 64) * 2;
#pragma unroll
    for (int i = t; i < 1024; i += 256) {      // A: 128 rows x 128B
        int r = i >> 3, j = (i & 7) * 16;
        uint32_t so = sw128(r * 128 + j);
        size_t  go = (size_t)r * (KTOT * 2) + j;
        cp16(stg + O_AH + so, ahg + go);
        cp16(stg + O_AL + so, alg + go);
    }
#pragma unroll
    for (int i = t; i < 2048; i += 256) {      // B: 256 rows x 128B
        int r = i >> 3, j = (i & 7) * 16;
        uint32_t so = sw128(r * 128 + j);
        size_t  go = (size_t)r * (KTOT * 2) + j;
        cp16(stg + O_BH + so, bhg + go);
        cp16(stg + O_BL + so, blg + go);
    }
    asm volatile("cp.async.commit_group;" ::: "memory");
}

__global__ __launch_bounds__(256) void gemm_mma_kernel(
    const float* __restrict__ b0, const float* __restrict__ b1,
    const float* __restrict__ b2, float* __restrict__ out)
{
    extern __shared__ char smem[];
    const uint32_t sb = smem_u32(smem);
    const int t = threadIdx.x, wid = t >> 5, lane = t & 31;
    const int m0 = blockIdx.x * 128;
    const int wm = wid & 1, wn = wid >> 1;        // 2 x 4 warp grid, warp tile 64x64

    float acc[4][8][4];
#pragma unroll
    for (int i = 0; i < 4; i++)
#pragma unroll
        for (int j = 0; j < 8; j++)
#pragma unroll
            for (int k = 0; k < 4; k++) acc[i][j][k] = 0.f;

    load_chunk(0, sb, t, m0);
    load_chunk(1, sb + STG_SZ, t, m0);

    const uint32_t arow  = (uint32_t)(wm * 64 + (lane & 15));                       // + mf*16
    const uint32_t acol8 = (uint32_t)(lane >> 4);
    const uint32_t brow  = (uint32_t)(wn * 64 + (lane & 7) + ((lane >> 4) & 1) * 8);// + nf2*16
    const uint32_t bcol8 = (uint32_t)((lane >> 3) & 1);

#pragma unroll 1
    for (int c = 0; c < NCHUNK; c++) {
        const uint32_t stg = sb + (uint32_t)(c & 1) * STG_SZ;

        asm volatile("cp.async.wait_group 1;" ::: "memory");
        __syncthreads();

#pragma unroll
        for (int ks = 0; ks < 4; ks++) {
            uint32_t ah[4][4], al[4][4];
#pragma unroll
            for (int mf = 0; mf < 4; mf++) {
                uint32_t off = sw128((arow + mf * 16) * 128 + (ks * 16 + acol8 * 8) * 2);
                ldm4(ah[mf], stg + O_AH + off);
                ldm4(al[mf], stg + O_AL + off);
            }
#pragma unroll
            for (int nf2 = 0; nf2 < 4; nf2++) {
                uint32_t bh[4], bl[4];
                uint32_t off = sw128((brow + nf2 * 16) * 128 + (ks * 16 + bcol8 * 8) * 2);
                ldm4(bh, stg + O_BH + off);
                ldm4(bl, stg + O_BL + off);
#pragma unroll
                for (int mf = 0; mf < 4; mf++)
#pragma unroll
                    for (int j = 0; j < 2; j++) {
                        float* a = acc[mf][nf2 * 2 + j];
                        mma_bf16(a, ah[mf], &bh[2 * j]);   // Ah*Bh
                        mma_bf16(a, ah[mf], &bl[2 * j]);   // Ah*Bl
                        mma_bf16(a, al[mf], &bh[2 * j]);   // Al*Bh
                    }
            }
        }

        __syncthreads();
        if (c + 2 < NCHUNK)
            load_chunk(c + 2, sb + (uint32_t)(c & 1) * STG_SZ, t, m0);
    }

    // ---- epilogue: flag-gated bias + relu ----
    const int gid = lane >> 2, t4 = lane & 3;
    float2 bb0[8], bb1[8], bb2[8];
#pragma unroll
    for (int nf = 0; nf < 8; nf++) {
        int col = wn * 64 + nf * 8 + t4 * 2;      // n0 = 0, full N in CTA
        bb0[nf] = *reinterpret_cast<const float2*>(b0 + col);
        bb1[nf] = *reinterpret_cast<const float2*>(b1 + col);
        bb2[nf] = *reinterpret_cast<const float2*>(b2 + col);
    }
#pragma unroll
    for (int mf = 0; mf < 4; mf++) {
#pragma unroll
        for (int half = 0; half < 2; half++) {
            int row = m0 + wm * 64 + mf * 16 + gid + half * 8;
            if (row >= NN) continue;
            float f0 = g_flg[row], f1 = g_flg[NN + row], f2 = g_flg[2 * NN + row];
#pragma unroll
            for (int nf = 0; nf < 8; nf++) {
                int col = wn * 64 + nf * 8 + t4 * 2;
                float2 o;
                o.x = fmaxf(acc[mf][nf][2 * half]     + f0 * bb0[nf].x + f1 * bb1[nf].x + f2 * bb2[nf].x, 0.f);
                o.y = fmaxf(acc[mf][nf][2 * half + 1] + f0 * bb0[nf].y + f1 * bb1[nf].y + f2 * bb2[nf].y, 0.f);
                *reinterpret_cast<float2*>(out + (size_t)row * DD + col) = o;
            }
        }
    }
}

// ================= launch =================
extern "C" void kernel_launch(void* const* d_in, const int* in_sizes, int n_in,
                              void* d_out, int out_size)
{
    const float* features = (const float*)d_in[0];
    const void*  src0 = d_in[1]; const void* dst0 = d_in[2];
    const void*  src1 = d_in[3]; const void* dst1 = d_in[4];
    const void*  src2 = d_in[5]; const void* dst2 = d_in[6];
    const float* W0 = (const float*)d_in[7];  const float* b0 = (const float*)d_in[8];
    const float* W1 = (const float*)d_in[9];  const float* b1 = (const float*)d_in[10];
    const float* W2 = (const float*)d_in[11]; const float* b2 = (const float*)d_in[12];
    float* out = (float*)d_out;

    cudaFuncSetAttribute(gemm_mma_kernel, cudaFuncAttributeMaxDynamicSharedMemorySize,
                         SMEM_GEMM);

    const int nScanBlocks = (NSEG3 + 255) / 256;   // 586

    detect_kernel<<<1, 32>>>((const int*)src0);
    zero_cnt_kernel<<<(NSEG3 + 255) / 256, 256>>>();

    {
        dim3 grid((EE + 255) / 256, 1, 3);
        hist_kernel<<<grid, 256>>>(dst0, dst1, dst2);
    }
    scan1_kernel<<<nScanBlocks, 256>>>();
    scan2_kernel<<<1, 1024>>>(nScanBlocks);
    {
        dim3 grid((EE + 255) / 256, 1, 3);
        scatter_kernel<<<grid, 256>>>(src0, dst0, src1, dst1, src2, dst2);
    }
    {
        int blocks = (NSEG3 * 32 + 255) / 256;
        node_gather_kernel<<<blocks, 256>>>(features);
    }
    {
        dim3 grid(DD / 32, DD / 32, 3);
        convertB_kernel<<<grid, dim3(32, 8)>>>(W0, W1, W2);
    }
    {
        dim3 grid(MPAD / 128, 1);                  // 391 CTAs, full N per CTA
        gemm_mma_kernel<<<grid, 256, SMEM_GEMM>>>(b0, b1, b2, out);
    }
}